// round 10
// baseline (speedup 1.0000x reference)
#include <cuda_runtime.h>
#include <math.h>

#define Sq  2048
#define Dd  512
#define Hh  8
#define DHh 64
#define CWw 128
#define NSPLIT 4
#define KSPL (Dd / NSPLIT)    // 128
#define NH   4                // window quarters

// ---------------- scratch (device globals) -------------------------------------
__device__ float g_cur[Sq * Dd];
__device__ float g_q[Sq * DHh];
__device__ float g_k[Sq * DHh];
__device__ float g_v[Sq * DHh];
__device__ float g_part[3][NSPLIT][Sq * DHh];
__device__ float g_pm[NH][Sq];            // partial softmax max
__device__ float g_ps[NH][Sq];            // partial softmax sum(exp)
__device__ float g_pv[NH][Sq * DHh];      // partial sum(exp * V)

// ---------------- init: cur = x -------------------------------------------------
__global__ void init_kernel(const float4* __restrict__ x) {
    int i = blockIdx.x * blockDim.x + threadIdx.x;
    ((float4*)g_cur)[i] = x[i];
}

// ---------------- qkv split-K partial GEMM (proven, at fp32 floor) --------------
__global__ __launch_bounds__(128) void qkv_partial(const float* __restrict__ Wq,
                                                   const float* __restrict__ Wk,
                                                   const float* __restrict__ Wvd, int h)
{
    __shared__ float Xs[32][36];
    __shared__ float Ws[32][68];

    const int sel = blockIdx.y;
    const int sp  = blockIdx.z;
    const float* B = (sel == 0 ? Wq : sel == 1 ? Wk : Wvd) + (size_t)h * DHh * Dd;
    float* C = &g_part[sel][sp][0];
    const int m0 = blockIdx.x * 32;
    const int kb = sp * KSPL;

    const int t  = threadIdx.x;
    const int tx = t & 15;
    const int ty = t >> 4;

    float acc[4][4] = {};

    for (int k0 = kb; k0 < kb + KSPL; k0 += 32) {
        #pragma unroll
        for (int r = 0; r < 2; r++) {
            int f = t + r * 128;
            int m = f >> 3, kv = f & 7;
            float4 va = *(const float4*)&g_cur[(size_t)(m0 + m) * Dd + k0 + kv * 4];
            Xs[kv * 4 + 0][m] = va.x;
            Xs[kv * 4 + 1][m] = va.y;
            Xs[kv * 4 + 2][m] = va.z;
            Xs[kv * 4 + 3][m] = va.w;
        }
        #pragma unroll
        for (int r = 0; r < 4; r++) {
            int f = t + r * 128;
            int n = f >> 3, kv = f & 7;
            float4 vb = *(const float4*)&B[(size_t)n * Dd + k0 + kv * 4];
            Ws[kv * 4 + 0][n] = vb.x;
            Ws[kv * 4 + 1][n] = vb.y;
            Ws[kv * 4 + 2][n] = vb.z;
            Ws[kv * 4 + 3][n] = vb.w;
        }
        __syncthreads();

        #pragma unroll
        for (int k = 0; k < 32; k++) {
            float4 a4 = *(const float4*)&Xs[k][ty * 4];
            float4 b4 = *(const float4*)&Ws[k][tx * 4];
            float a[4] = {a4.x, a4.y, a4.z, a4.w};
            float b[4] = {b4.x, b4.y, b4.z, b4.w};
            #pragma unroll
            for (int i = 0; i < 4; i++)
                #pragma unroll
                for (int j = 0; j < 4; j++)
                    acc[i][j] = fmaf(a[i], b[j], acc[i][j]);
        }
        __syncthreads();
    }

    #pragma unroll
    for (int i = 0; i < 4; i++) {
        float4 o = make_float4(acc[i][0], acc[i][1], acc[i][2], acc[i][3]);
        *(float4*)&C[(size_t)(m0 + ty * 4 + i) * DHh + tx * 4] = o;
    }
}

__global__ void qkv_reduce()
{
    const int sel = blockIdx.y;
    const int i = blockIdx.x * 256 + threadIdx.x;
    float4 a = ((const float4*)&g_part[sel][0][0])[i];
    float4 b = ((const float4*)&g_part[sel][1][0])[i];
    float4 c = ((const float4*)&g_part[sel][2][0])[i];
    float4 d = ((const float4*)&g_part[sel][3][0])[i];
    float4 o;
    o.x = (a.x + b.x) + (c.x + d.x);
    o.y = (a.y + b.y) + (c.y + d.y);
    o.z = (a.z + b.z) + (c.z + d.z);
    o.w = (a.w + b.w) + (c.w + d.w);
    float* out = (sel == 0 ? g_q : sel == 1 ? g_k : g_v);
    ((float4*)out)[i] = o;
}

// ---------------- attention, window split into 4 quarters ------------------------
// grid (S/16, 4). Quarter hf handles relative slots r in [64hf, 64hf+64) of each
// query's 256-wide window. Local key index kk = q + (r - 64hf) in [q, q+64);
// global key = kstart + kk, kstart = j0 - 128 + 64*hf. KH = 64 + 15 + 1 = 80 rows.
#define HT   16
#define KH   80
#define KHP  68
#define PP3  84

#define ASM_K  0
#define ASM_P  8192                  // region A sized for Rs overlay (8*16*64)
#define ASM_Q  (ASM_P + HT * PP3)    // 8192 + 1344 = 9536
#define ASM_T  (ASM_Q + HT * DHh)    // 10560 floats = 42240 B

__global__ __launch_bounds__(256) void attn_quarter()
{
    extern __shared__ float sm[];
    float* Ks = sm + ASM_K;          // [80][68] (first 5440 floats of region A)
    float* Ps = sm + ASM_P;          // [16][84] exp weights
    float* Qs = sm + ASM_Q;          // [16][64]
    float* Rs = sm + ASM_K;          // AV partials overlay region A (8192 floats)

    const int t    = threadIdx.x;    // 256
    const int w    = t >> 5;
    const int lane = t & 31;
    const int j0   = blockIdx.x * HT;
    const int hf   = blockIdx.y;
    const int kstart = j0 - CWw + 64 * hf;

    // ---- stage K segment (80 rows, zero-filled OOB) + Q tile
    for (int f = t; f < KH * 16; f += 256) {
        int kk = f >> 4, d4 = f & 15;
        int gk = kstart + kk;
        float4 kv = make_float4(0.f, 0.f, 0.f, 0.f);
        if (gk >= 0 && gk < Sq) kv = ((const float4*)&g_k[(size_t)gk * DHh])[d4];
        *(float4*)&Ks[kk * KHP + d4 * 4] = kv;
    }
    {
        int q = t >> 4, d4 = t & 15;
        ((float4*)&Qs[q * DHh])[d4] = ((const float4*)&g_q[(size_t)(j0 + q) * DHh])[d4];
    }
    __syncthreads();

    // ---- scores: warp w owns queries q0=2w, q1=2w+1; lane covers kk=lane+32jj, jj<3
    const int q0 = 2 * w, q1 = 2 * w + 1;
    {
        float a0[3] = {}, a1[3] = {};
        #pragma unroll
        for (int d4 = 0; d4 < 16; d4++) {
            float4 qa = *(const float4*)&Qs[q0 * DHh + d4 * 4];
            float4 qb = *(const float4*)&Qs[q1 * DHh + d4 * 4];
            #pragma unroll
            for (int jj = 0; jj < 3; jj++) {
                int kk = lane + 32 * jj;
                int kks = kk < KH - 1 ? kk : KH - 1;   // clamp (masked below)
                const float4 kv = *(const float4*)&Ks[kks * KHP + d4 * 4];
                a0[jj] = fmaf(kv.x, qa.x, fmaf(kv.y, qa.y, fmaf(kv.z, qa.z, fmaf(kv.w, qa.w, a0[jj]))));
                a1[jj] = fmaf(kv.x, qb.x, fmaf(kv.y, qb.y, fmaf(kv.z, qb.z, fmaf(kv.w, qb.w, a1[jj]))));
            }
        }
        float m0 = -1e30f, m1 = -1e30f;
        #pragma unroll
        for (int jj = 0; jj < 3; jj++) {
            int kk = lane + 32 * jj;
            int gk = kstart + kk;
            bool gok = (gk >= 0) && (gk < Sq);
            bool v0 = gok && (kk >= q0) && (kk < q0 + 64);
            bool v1 = gok && (kk >= q1) && (kk < q1 + 64);
            a0[jj] = v0 ? a0[jj] * 0.125f : -1e30f;
            a1[jj] = v1 ? a1[jj] * 0.125f : -1e30f;
            m0 = fmaxf(m0, a0[jj]);
            m1 = fmaxf(m1, a1[jj]);
        }
        #pragma unroll
        for (int o = 16; o; o >>= 1) {
            m0 = fmaxf(m0, __shfl_xor_sync(0xffffffffu, m0, o));
            m1 = fmaxf(m1, __shfl_xor_sync(0xffffffffu, m1, o));
        }
        float s0 = 0.f, s1 = 0.f;
        #pragma unroll
        for (int jj = 0; jj < 3; jj++) {
            int kk = lane + 32 * jj;
            float e0 = __expf(a0[jj] - m0);   // masked: underflow->0 (or m=-1e30, weight 0 at combine)
            float e1 = __expf(a1[jj] - m1);
            s0 += e0;
            s1 += e1;
            if (kk < KH) {
                Ps[q0 * PP3 + kk] = e0;
                Ps[q1 * PP3 + kk] = e1;
            }
        }
        #pragma unroll
        for (int o = 16; o; o >>= 1) {
            s0 += __shfl_xor_sync(0xffffffffu, s0, o);
            s1 += __shfl_xor_sync(0xffffffffu, s1, o);
        }
        if (lane == 0) {
            g_pm[hf][j0 + q0] = m0;
            g_pm[hf][j0 + q1] = m1;
            g_ps[hf][j0 + q0] = s0;
            g_ps[hf][j0 + q1] = s1;
        }
    }
    __syncthreads();   // Ps done; Ks dead (Ps region untouched by Rs)

    // ---- AV (unnormalized): warp w owns keys [10w, 10w+10); V streamed from L2
    {
        const int qh = (lane >> 4) * 8;
        const int d4 = lane & 15;
        float4 r[8] = {};
        #pragma unroll
        for (int i = 0; i < 10; i++) {
            int kk = w * 10 + i;
            int gk = kstart + kk;
            float4 v4 = make_float4(0.f, 0.f, 0.f, 0.f);
            if (gk >= 0 && gk < Sq)
                v4 = ((const float4*)&g_v[(size_t)gk * DHh])[d4];
            #pragma unroll
            for (int qi = 0; qi < 8; qi++) {
                float p = Ps[(qh + qi) * PP3 + kk];
                r[qi].x = fmaf(p, v4.x, r[qi].x);
                r[qi].y = fmaf(p, v4.y, r[qi].y);
                r[qi].z = fmaf(p, v4.z, r[qi].z);
                r[qi].w = fmaf(p, v4.w, r[qi].w);
            }
        }
        #pragma unroll
        for (int qi = 0; qi < 8; qi++)
            *(float4*)&Rs[(w * HT + qh + qi) * DHh + d4 * 4] = r[qi];
    }
    __syncthreads();

    // reduce 8 warp-partials -> g_pv (16 x 64)
    #pragma unroll
    for (int ii = 0; ii < 4; ii++) {
        int idx = t + 256 * ii;          // 0..1023
        int q = idx >> 6, d = idx & 63;
        float s = 0.f;
        #pragma unroll
        for (int ww = 0; ww < 8; ww++) s += Rs[(ww * HT + q) * DHh + d];
        g_pv[hf][(size_t)(j0 + q) * DHh + d] = s;
    }
}

// ---------------- fused combine + up-projection + residual + renorm -------------
// R6-proven: 16 tokens/block, 256 threads, full Wvu head slice in smem [k][n].
#define WP 516

__global__ __launch_bounds__(256) void upnorm_kernel(const float* __restrict__ Wvu,
                                                     int h, int last,
                                                     float* __restrict__ out)
{
    extern __shared__ float sm[];
    float* Ws = sm;                 // [64][516]
    float* As = sm + 64 * WP;       // [16][64]

    const int t  = threadIdx.x;     // 256
    const int m0 = blockIdx.x * 16;
    const float* W = Wvu + (size_t)h * Dd * DHh;

    { // load + transpose Wvu (R6 proven)
        int k4 = t >> 4;
        int nb = t & 15;
        for (int i = 0; i < 32; i++) {
            int n = nb + 16 * i;
            float4 wv = *(const float4*)&W[(size_t)n * DHh + k4 * 4];
            Ws[(4 * k4 + 0) * WP + n] = wv.x;
            Ws[(4 * k4 + 1) * WP + n] = wv.y;
            Ws[(4 * k4 + 2) * WP + n] = wv.z;
            Ws[(4 * k4 + 3) * WP + n] = wv.w;
        }
    }
    // combine NH softmax quarters -> As (16 x 64)
    #pragma unroll
    for (int ii = 0; ii < 4; ii++) {
        int idx = t + 256 * ii;          // 0..1023
        int q = idx >> 6, d = idx & 63;
        int m = m0 + q;
        float M = -1e30f;
        #pragma unroll
        for (int hh = 0; hh < NH; hh++) M = fmaxf(M, g_pm[hh][m]);
        float denom = 0.f, pv = 0.f;
        #pragma unroll
        for (int hh = 0; hh < NH; hh++) {
            float c = __expf(g_pm[hh][m] - M);
            denom = fmaf(c, g_ps[hh][m], denom);
            pv    = fmaf(c, g_pv[hh][(size_t)m * DHh + d], pv);
        }
        As[q * DHh + d] = pv / denom;
    }
    __syncthreads();

    const int w    = t >> 5;
    const int lane = t & 31;
    const int r0 = m0 + 2 * w, r1 = r0 + 1;

    float4 y0[4] = {}, y1[4] = {};
    for (int k = 0; k < DHh; k++) {
        float av0 = As[(2 * w) * DHh + k];
        float av1 = As[(2 * w + 1) * DHh + k];
        #pragma unroll
        for (int j = 0; j < 4; j++) {
            float4 wv = *(const float4*)&Ws[k * WP + 4 * (lane + 32 * j)];
            y0[j].x = fmaf(av0, wv.x, y0[j].x);
            y0[j].y = fmaf(av0, wv.y, y0[j].y);
            y0[j].z = fmaf(av0, wv.z, y0[j].z);
            y0[j].w = fmaf(av0, wv.w, y0[j].w);
            y1[j].x = fmaf(av1, wv.x, y1[j].x);
            y1[j].y = fmaf(av1, wv.y, y1[j].y);
            y1[j].z = fmaf(av1, wv.z, y1[j].z);
            y1[j].w = fmaf(av1, wv.w, y1[j].w);
        }
    }

    float4 c0[4], c1[4];
    #pragma unroll
    for (int j = 0; j < 4; j++) {
        c0[j] = ((const float4*)&g_cur[(size_t)r0 * Dd])[lane + 32 * j];
        c1[j] = ((const float4*)&g_cur[(size_t)r1 * Dd])[lane + 32 * j];
        y0[j].x += c0[j].x; y0[j].y += c0[j].y; y0[j].z += c0[j].z; y0[j].w += c0[j].w;
        y1[j].x += c1[j].x; y1[j].y += c1[j].y; y1[j].z += c1[j].z; y1[j].w += c1[j].w;
    }

    float t0 = 0.f, t1 = 0.f;
    #pragma unroll
    for (int j = 0; j < 4; j++) {
        t0 += y0[j].x + y0[j].y + y0[j].z + y0[j].w;
        t1 += y1[j].x + y1[j].y + y1[j].z + y1[j].w;
    }
    #pragma unroll
    for (int o = 16; o; o >>= 1) {
        t0 += __shfl_xor_sync(0xffffffffu, t0, o);
        t1 += __shfl_xor_sync(0xffffffffu, t1, o);
    }
    float im0 = 512.f / t0, im1 = 512.f / t1;
    #pragma unroll
    for (int j = 0; j < 4; j++) {
        y0[j].x *= im0; y0[j].y *= im0; y0[j].z *= im0; y0[j].w *= im0;
        y1[j].x *= im1; y1[j].y *= im1; y1[j].z *= im1; y1[j].w *= im1;
    }
    t0 = 0.f; t1 = 0.f;
    #pragma unroll
    for (int j = 0; j < 4; j++) {
        t0 += y0[j].x + y0[j].y + y0[j].z + y0[j].w;
        t1 += y1[j].x + y1[j].y + y1[j].z + y1[j].w;
    }
    #pragma unroll
    for (int o = 16; o; o >>= 1) {
        t0 += __shfl_xor_sync(0xffffffffu, t0, o);
        t1 += __shfl_xor_sync(0xffffffffu, t1, o);
    }
    float mu0 = t0 * (1.f / 512.f), mu1 = t1 * (1.f / 512.f);
    float v0 = 0.f, v1 = 0.f;
    #pragma unroll
    for (int j = 0; j < 4; j++) {
        y0[j].x -= mu0; y0[j].y -= mu0; y0[j].z -= mu0; y0[j].w -= mu0;
        y1[j].x -= mu1; y1[j].y -= mu1; y1[j].z -= mu1; y1[j].w -= mu1;
        v0 += y0[j].x*y0[j].x + y0[j].y*y0[j].y + y0[j].z*y0[j].z + y0[j].w*y0[j].w;
        v1 += y1[j].x*y1[j].x + y1[j].y*y1[j].y + y1[j].z*y1[j].z + y1[j].w*y1[j].w;
    }
    #pragma unroll
    for (int o = 16; o; o >>= 1) {
        v0 += __shfl_xor_sync(0xffffffffu, v0, o);
        v1 += __shfl_xor_sync(0xffffffffu, v1, o);
    }
    float is0 = rsqrtf(v0 * (1.f / 511.f));
    float is1 = rsqrtf(v1 * (1.f / 511.f));

    #pragma unroll
    for (int j = 0; j < 4; j++) {
        float4 n0, n1;
        n0.x = c0[j].x + y0[j].x * is0 + mu0;
        n0.y = c0[j].y + y0[j].y * is0 + mu0;
        n0.z = c0[j].z + y0[j].z * is0 + mu0;
        n0.w = c0[j].w + y0[j].w * is0 + mu0;
        n1.x = c1[j].x + y1[j].x * is1 + mu1;
        n1.y = c1[j].y + y1[j].y * is1 + mu1;
        n1.z = c1[j].z + y1[j].z * is1 + mu1;
        n1.w = c1[j].w + y1[j].w * is1 + mu1;
        ((float4*)&g_cur[(size_t)r0 * Dd])[lane + 32 * j] = n0;
        ((float4*)&g_cur[(size_t)r1 * Dd])[lane + 32 * j] = n1;
        if (last) {
            n0.x *= 0.125f; n0.y *= 0.125f; n0.z *= 0.125f; n0.w *= 0.125f;
            n1.x *= 0.125f; n1.y *= 0.125f; n1.z *= 0.125f; n1.w *= 0.125f;
            ((float4*)&out[(size_t)r0 * Dd])[lane + 32 * j] = n0;
            ((float4*)&out[(size_t)r1 * Dd])[lane + 32 * j] = n1;
        }
    }
}

// ---------------- launch ---------------------------------------------------------
extern "C" void kernel_launch(void* const* d_in, const int* in_sizes, int n_in,
                              void* d_out, int out_size)
{
    const float* x   = (const float*)d_in[0];
    const float* Wq  = (const float*)d_in[1];
    const float* Wk  = (const float*)d_in[2];
    const float* Wvd = (const float*)d_in[3];
    const float* Wvu = (const float*)d_in[4];
    float* out = (float*)d_out;

    const int attn_smem = ASM_T * 4;                 // 42240 B
    const int up_smem   = (64 * WP + 16 * DHh) * 4;  // 136192 B
    cudaFuncSetAttribute(attn_quarter, cudaFuncAttributeMaxDynamicSharedMemorySize, attn_smem);
    cudaFuncSetAttribute(upnorm_kernel, cudaFuncAttributeMaxDynamicSharedMemorySize, up_smem);

    init_kernel<<<(Sq * Dd / 4) / 256, 256>>>((const float4*)x);
    for (int h = 0; h < Hh; h++) {
        qkv_partial<<<dim3(Sq / 32, 3, NSPLIT), 128>>>(Wq, Wk, Wvd, h);
        qkv_reduce<<<dim3(Sq * DHh / 4 / 256, 3), 256>>>();
        attn_quarter<<<dim3(Sq / HT, NH), 256, attn_smem>>>();
        upnorm_kernel<<<Sq / 16, 256, up_smem>>>(Wvu, h, h == Hh - 1 ? 1 : 0, out);
    }
}

// round 11
// speedup vs baseline: 1.1917x; 1.1917x over previous
#include <cuda_runtime.h>
#include <math.h>

#define Sq  2048
#define Dd  512
#define Hh  8
#define DHh 64
#define CWw 128
#define NSPLIT 4
#define KSPL (Dd / NSPLIT)    // 128

// ---------------- scratch (device globals) -------------------------------------
__device__ float g_cur[Sq * Dd];
__device__ float g_q[Sq * DHh];
__device__ float g_k[Sq * DHh];
__device__ float g_v[Sq * DHh];
__device__ float g_part[3][NSPLIT][Sq * DHh];
__device__ float g_pm[2][Sq];            // partial softmax max
__device__ float g_ps[2][Sq];            // partial softmax sum(exp)
__device__ float g_pv[2][Sq * DHh];      // partial sum(exp * V)

// ---------------- init: cur = x -------------------------------------------------
__global__ void init_kernel(const float4* __restrict__ x) {
    int i = blockIdx.x * blockDim.x + threadIdx.x;
    ((float4*)g_cur)[i] = x[i];
}

// ---------------- qkv split-K partial GEMM (proven, at fp32 floor) --------------
__global__ __launch_bounds__(128) void qkv_partial(const float* __restrict__ Wq,
                                                   const float* __restrict__ Wk,
                                                   const float* __restrict__ Wvd, int h)
{
    __shared__ float Xs[32][36];
    __shared__ float Ws[32][68];

    const int sel = blockIdx.y;
    const int sp  = blockIdx.z;
    const float* B = (sel == 0 ? Wq : sel == 1 ? Wk : Wvd) + (size_t)h * DHh * Dd;
    float* C = &g_part[sel][sp][0];
    const int m0 = blockIdx.x * 32;
    const int kb = sp * KSPL;

    const int t  = threadIdx.x;
    const int tx = t & 15;
    const int ty = t >> 4;

    float acc[4][4] = {};

    for (int k0 = kb; k0 < kb + KSPL; k0 += 32) {
        #pragma unroll
        for (int r = 0; r < 2; r++) {
            int f = t + r * 128;
            int m = f >> 3, kv = f & 7;
            float4 va = *(const float4*)&g_cur[(size_t)(m0 + m) * Dd + k0 + kv * 4];
            Xs[kv * 4 + 0][m] = va.x;
            Xs[kv * 4 + 1][m] = va.y;
            Xs[kv * 4 + 2][m] = va.z;
            Xs[kv * 4 + 3][m] = va.w;
        }
        #pragma unroll
        for (int r = 0; r < 4; r++) {
            int f = t + r * 128;
            int n = f >> 3, kv = f & 7;
            float4 vb = *(const float4*)&B[(size_t)n * Dd + k0 + kv * 4];
            Ws[kv * 4 + 0][n] = vb.x;
            Ws[kv * 4 + 1][n] = vb.y;
            Ws[kv * 4 + 2][n] = vb.z;
            Ws[kv * 4 + 3][n] = vb.w;
        }
        __syncthreads();

        #pragma unroll
        for (int k = 0; k < 32; k++) {
            float4 a4 = *(const float4*)&Xs[k][ty * 4];
            float4 b4 = *(const float4*)&Ws[k][tx * 4];
            float a[4] = {a4.x, a4.y, a4.z, a4.w};
            float b[4] = {b4.x, b4.y, b4.z, b4.w};
            #pragma unroll
            for (int i = 0; i < 4; i++)
                #pragma unroll
                for (int j = 0; j < 4; j++)
                    acc[i][j] = fmaf(a[i], b[j], acc[i][j]);
        }
        __syncthreads();
    }

    #pragma unroll
    for (int i = 0; i < 4; i++) {
        float4 o = make_float4(acc[i][0], acc[i][1], acc[i][2], acc[i][3]);
        *(float4*)&C[(size_t)(m0 + ty * 4 + i) * DHh + tx * 4] = o;
    }
}

__global__ void qkv_reduce()
{
    const int sel = blockIdx.y;
    const int i = blockIdx.x * 256 + threadIdx.x;
    float4 a = ((const float4*)&g_part[sel][0][0])[i];
    float4 b = ((const float4*)&g_part[sel][1][0])[i];
    float4 c = ((const float4*)&g_part[sel][2][0])[i];
    float4 d = ((const float4*)&g_part[sel][3][0])[i];
    float4 o;
    o.x = (a.x + b.x) + (c.x + d.x);
    o.y = (a.y + b.y) + (c.y + d.y);
    o.z = (a.z + b.z) + (c.z + d.z);
    o.w = (a.w + b.w) + (c.w + d.w);
    float* out = (sel == 0 ? g_q : sel == 1 ? g_k : g_v);
    ((float4*)out)[i] = o;
}

// ---------------- attention, window-split halves (R9 proven: 13.6us) ------------
#define HT   16
#define KH   144
#define KHP  68
#define PP2  148

#define ASM_K  0
#define ASM_P  (KH * KHP)            // 9792
#define ASM_Q  (ASM_P + HT * PP2)    // +2368
#define ASM_T  (ASM_Q + HT * DHh)    // 13184 floats = 52736 B

__global__ __launch_bounds__(256) void attn_half()
{
    extern __shared__ float sm[];
    float* Ks = sm + ASM_K;
    float* Ps = sm + ASM_P;
    float* Qs = sm + ASM_Q;
    float* Rs = sm + ASM_K;          // AV partials overlay Ks (8192 <= 9792)

    const int t    = threadIdx.x;    // 256
    const int w    = t >> 5;
    const int lane = t & 31;
    const int j0   = blockIdx.x * HT;
    const int hf   = blockIdx.y;
    const int kstart = j0 - CWw + 128 * hf;

    for (int f = t; f < KH * 16; f += 256) {
        int kk = f >> 4, d4 = f & 15;
        int gk = kstart + kk;
        float4 kv = make_float4(0.f, 0.f, 0.f, 0.f);
        if (gk >= 0 && gk < Sq) kv = ((const float4*)&g_k[(size_t)gk * DHh])[d4];
        *(float4*)&Ks[kk * KHP + d4 * 4] = kv;
    }
    {
        int q = t >> 4, d4 = t & 15;
        ((float4*)&Qs[q * DHh])[d4] = ((const float4*)&g_q[(size_t)(j0 + q) * DHh])[d4];
    }
    __syncthreads();

    const int q0 = 2 * w, q1 = 2 * w + 1;
    {
        float a0[5] = {}, a1[5] = {};
        #pragma unroll
        for (int d4 = 0; d4 < 16; d4++) {
            float4 qa = *(const float4*)&Qs[q0 * DHh + d4 * 4];
            float4 qb = *(const float4*)&Qs[q1 * DHh + d4 * 4];
            #pragma unroll
            for (int jj = 0; jj < 5; jj++) {
                int kk = lane + 32 * jj;
                int kks = kk < KH - 1 ? kk : KH - 1;
                const float4 kv = *(const float4*)&Ks[kks * KHP + d4 * 4];
                a0[jj] = fmaf(kv.x, qa.x, fmaf(kv.y, qa.y, fmaf(kv.z, qa.z, fmaf(kv.w, qa.w, a0[jj]))));
                a1[jj] = fmaf(kv.x, qb.x, fmaf(kv.y, qb.y, fmaf(kv.z, qb.z, fmaf(kv.w, qb.w, a1[jj]))));
            }
        }
        float m0 = -1e30f, m1 = -1e30f;
        #pragma unroll
        for (int jj = 0; jj < 5; jj++) {
            int kk = lane + 32 * jj;
            int gk = kstart + kk;
            bool gok = (gk >= 0) && (gk < Sq);
            bool v0 = gok && (kk >= q0) && (kk < q0 + 128);
            bool v1 = gok && (kk >= q1) && (kk < q1 + 128);
            a0[jj] = v0 ? a0[jj] * 0.125f : -1e30f;
            a1[jj] = v1 ? a1[jj] * 0.125f : -1e30f;
            m0 = fmaxf(m0, a0[jj]);
            m1 = fmaxf(m1, a1[jj]);
        }
        #pragma unroll
        for (int o = 16; o; o >>= 1) {
            m0 = fmaxf(m0, __shfl_xor_sync(0xffffffffu, m0, o));
            m1 = fmaxf(m1, __shfl_xor_sync(0xffffffffu, m1, o));
        }
        float s0 = 0.f, s1 = 0.f;
        #pragma unroll
        for (int jj = 0; jj < 5; jj++) {
            int kk = lane + 32 * jj;
            float e0 = __expf(a0[jj] - m0);
            float e1 = __expf(a1[jj] - m1);
            s0 += e0;
            s1 += e1;
            if (kk < KH) {
                Ps[q0 * PP2 + kk] = e0;
                Ps[q1 * PP2 + kk] = e1;
            }
        }
        #pragma unroll
        for (int o = 16; o; o >>= 1) {
            s0 += __shfl_xor_sync(0xffffffffu, s0, o);
            s1 += __shfl_xor_sync(0xffffffffu, s1, o);
        }
        if (lane == 0) {
            g_pm[hf][j0 + q0] = m0;
            g_pm[hf][j0 + q1] = m1;
            g_ps[hf][j0 + q0] = s0;
            g_ps[hf][j0 + q1] = s1;
        }
    }
    __syncthreads();

    {
        const int qh = (lane >> 4) * 8;
        const int d4 = lane & 15;
        float4 r[8] = {};
        #pragma unroll
        for (int i = 0; i < 18; i++) {
            int kk = w * 18 + i;
            int gk = kstart + kk;
            float4 v4 = make_float4(0.f, 0.f, 0.f, 0.f);
            if (gk >= 0 && gk < Sq)
                v4 = ((const float4*)&g_v[(size_t)gk * DHh])[d4];
            #pragma unroll
            for (int qi = 0; qi < 8; qi++) {
                float p = Ps[(qh + qi) * PP2 + kk];
                r[qi].x = fmaf(p, v4.x, r[qi].x);
                r[qi].y = fmaf(p, v4.y, r[qi].y);
                r[qi].z = fmaf(p, v4.z, r[qi].z);
                r[qi].w = fmaf(p, v4.w, r[qi].w);
            }
        }
        #pragma unroll
        for (int qi = 0; qi < 8; qi++)
            *(float4*)&Rs[(w * HT + qh + qi) * DHh + d4 * 4] = r[qi];
    }
    __syncthreads();

    #pragma unroll
    for (int ii = 0; ii < 4; ii++) {
        int idx = t + 256 * ii;
        int q = idx >> 6, d = idx & 63;
        float s = 0.f;
        #pragma unroll
        for (int ww = 0; ww < 8; ww++) s += Rs[(ww * HT + q) * DHh + d];
        g_pv[hf][(size_t)(j0 + q) * DHh + d] = s;
    }
}

// ---------------- fused combine + up-projection + residual + renorm -------------
// 16 tokens/block, 256 threads, W in natural [n][k] layout (NO transpose).
#define WPn 68    // row pitch for W rows (64 + 4)

__global__ __launch_bounds__(256) void upnorm_kernel(const float* __restrict__ Wvu,
                                                     int h, int last,
                                                     float* __restrict__ out)
{
    extern __shared__ float sm[];
    float* Ws = sm;                  // [512][68]
    float* As = sm + Dd * WPn;       // [16][64]

    const int t    = threadIdx.x;    // 256
    const int w    = t >> 5;
    const int lane = t & 31;
    const int m0   = blockIdx.x * 16;
    const float* Wg = Wvu + (size_t)h * Dd * DHh;

    // ---- straight copy of W (512 x 64), float4 in/out, no transpose
    #pragma unroll
    for (int r = 0; r < 32; r++) {
        int f = t + r * 256;
        int row = f >> 4, k4 = f & 15;
        *(float4*)&Ws[row * WPn + k4 * 4] =
            *(const float4*)&Wg[(size_t)row * DHh + k4 * 4];
    }

    // ---- combine 2 softmax halves -> As (16 x 64)
    #pragma unroll
    for (int ii = 0; ii < 4; ii++) {
        int idx = t + 256 * ii;          // 0..1023
        int q = idx >> 6, d = idx & 63;
        int m = m0 + q;
        float ma = g_pm[0][m], mb = g_pm[1][m];
        float M  = fmaxf(ma, mb);
        float ca = __expf(ma - M), cb = __expf(mb - M);
        float denom = ca * g_ps[0][m] + cb * g_ps[1][m];
        float pv = ca * g_pv[0][(size_t)m * DHh + d] + cb * g_pv[1][(size_t)m * DHh + d];
        As[q * DHh + d] = pv / denom;
    }
    __syncthreads();

    // ---- up GEMM: warp owns tokens 2w, 2w+1; lane owns n = lane + 32j (j<16)
    const int tok0 = 2 * w, tok1 = 2 * w + 1;
    float acc0[16] = {}, acc1[16] = {};
    #pragma unroll
    for (int k4 = 0; k4 < 16; k4++) {
        float4 a0 = *(const float4*)&As[tok0 * DHh + k4 * 4];
        float4 a1 = *(const float4*)&As[tok1 * DHh + k4 * 4];
        #pragma unroll
        for (int j = 0; j < 16; j++) {
            float4 wv = *(const float4*)&Ws[(lane + 32 * j) * WPn + k4 * 4];
            acc0[j] = fmaf(a0.x, wv.x, fmaf(a0.y, wv.y, fmaf(a0.z, wv.z, fmaf(a0.w, wv.w, acc0[j]))));
            acc1[j] = fmaf(a1.x, wv.x, fmaf(a1.y, wv.y, fmaf(a1.z, wv.z, fmaf(a1.w, wv.w, acc1[j]))));
        }
    }

    // ---- residual + renorm, token tok0 then tok1 (limits register pressure)
    #pragma unroll
    for (int tk = 0; tk < 2; tk++) {
        const int m = m0 + 2 * w + tk;
        const float* accp = tk == 0 ? acc0 : acc1;
        float cres[16], y[16];
        float s = 0.f;
        #pragma unroll
        for (int j = 0; j < 16; j++) {
            int n = lane + 32 * j;
            cres[j] = g_cur[(size_t)m * Dd + n];
            y[j] = accp[j] + cres[j];
            s += y[j];
        }
        #pragma unroll
        for (int o = 16; o; o >>= 1) s += __shfl_xor_sync(0xffffffffu, s, o);
        float im = 512.f / s;                       // 1/m1
        s = 0.f;
        #pragma unroll
        for (int j = 0; j < 16; j++) { y[j] *= im; s += y[j]; }
        #pragma unroll
        for (int o = 16; o; o >>= 1) s += __shfl_xor_sync(0xffffffffu, s, o);
        float m2 = s * (1.f / 512.f);
        float v = 0.f;
        #pragma unroll
        for (int j = 0; j < 16; j++) { y[j] -= m2; v += y[j] * y[j]; }
        #pragma unroll
        for (int o = 16; o; o >>= 1) v += __shfl_xor_sync(0xffffffffu, v, o);
        float is = rsqrtf(v * (1.f / 511.f));

        #pragma unroll
        for (int j = 0; j < 16; j++) {
            int n = lane + 32 * j;
            float nv = cres[j] + y[j] * is + m2;
            g_cur[(size_t)m * Dd + n] = nv;
            if (last) out[(size_t)m * Dd + n] = nv * 0.125f;
        }
    }
}

// ---------------- launch ---------------------------------------------------------
extern "C" void kernel_launch(void* const* d_in, const int* in_sizes, int n_in,
                              void* d_out, int out_size)
{
    const float* x   = (const float*)d_in[0];
    const float* Wq  = (const float*)d_in[1];
    const float* Wk  = (const float*)d_in[2];
    const float* Wvd = (const float*)d_in[3];
    const float* Wvu = (const float*)d_in[4];
    float* out = (float*)d_out;

    const int attn_smem = ASM_T * 4;                      // 52736 B
    const int up_smem   = (Dd * WPn + 16 * DHh) * 4;      // 143360 B
    cudaFuncSetAttribute(attn_half, cudaFuncAttributeMaxDynamicSharedMemorySize, attn_smem);
    cudaFuncSetAttribute(upnorm_kernel, cudaFuncAttributeMaxDynamicSharedMemorySize, up_smem);

    init_kernel<<<(Sq * Dd / 4) / 256, 256>>>((const float4*)x);
    for (int h = 0; h < Hh; h++) {
        qkv_partial<<<dim3(Sq / 32, 3, NSPLIT), 128>>>(Wq, Wk, Wvd, h);
        qkv_reduce<<<dim3(Sq * DHh / 4 / 256, 3), 256>>>();
        attn_half<<<dim3(Sq / HT, 2), 256, attn_smem>>>();
        upnorm_kernel<<<Sq / 16, 256, up_smem>>>(Wvu, h, h == Hh - 1 ? 1 : 0, out);
    }
}